// round 14
// baseline (speedup 1.0000x reference)
#include <cuda_runtime.h>
#include <cuda_bf16.h>
#include <math.h>
#include <stdint.h>

#define N_NODES 50000
#define N_EDGES 800000
#define F_IN    128
#define HID     64
#define H1      3
#define D1      (H1*HID)        // 192
#define OUT     64
#define LRELU   0.2f
#define NBLK    ((N_NODES + 255) / 256)   // 196

// ---------------- scratch (device globals; no allocation allowed) ----------------
__device__ int   g_is64;
__device__ int   g_cnt[N_NODES];
__device__ int   g_bsum[256];
__device__ int   g_boff[256];
__device__ int   g_rowoff[N_NODES + 1];
__device__ int   g_cur[N_NODES];
__device__ int2  g_epack[N_EDGES];              // {src, float_bits(edge_attr)}
__device__ float g_xw1[(size_t)N_NODES * 384];  // [node][xl(192) | xr(192)]
__device__ float g_h1[(size_t)N_NODES * D1];
__device__ float g_xw2[(size_t)N_NODES * 128];  // [node][xl(64) | xr(64)]

// ---------------- helpers ----------------
__device__ __forceinline__ float lrelu(float v) { return v > 0.f ? v : LRELU * v; }
__device__ __forceinline__ float elu(float v)   { return v > 0.f ? v : expm1f(v); }

__device__ __forceinline__ uint32_t smem_u32(const void* p) {
    uint32_t a;
    asm("{ .reg .u64 t; cvta.to.shared.u64 t, %1; cvt.u32.u64 %0, t; }"
        : "=r"(a) : "l"(p));
    return a;
}
#define LDSM_X4(r, addr) \
    asm volatile("ldmatrix.sync.aligned.m8n8.x4.shared.b16 {%0,%1,%2,%3}, [%4];" \
        : "=r"((r)[0]), "=r"((r)[1]), "=r"((r)[2]), "=r"((r)[3]) : "r"(addr))

__device__ __forceinline__ void mma_bf16(float* c, const uint32_t* a,
                                         uint32_t b0, uint32_t b1) {
    asm volatile(
        "mma.sync.aligned.m16n8k16.row.col.f32.bf16.bf16.f32 "
        "{%0,%1,%2,%3}, {%4,%5,%6,%7}, {%8,%9}, {%0,%1,%2,%3};"
        : "+f"(c[0]), "+f"(c[1]), "+f"(c[2]), "+f"(c[3])
        : "r"(a[0]), "r"(a[1]), "r"(a[2]), "r"(a[3]), "r"(b0), "r"(b1));
}

// split v into bf16 hi + bf16 lo (v - hi exact in fp32; two-term split)
__device__ __forceinline__ void bf16_split8(const float* v, uint32_t* hw, uint32_t* lw) {
#pragma unroll
    for (int j = 0; j < 4; j++) {
        __nv_bfloat16 h0 = __float2bfloat16(v[2 * j]);
        __nv_bfloat16 h1 = __float2bfloat16(v[2 * j + 1]);
        __nv_bfloat16 l0 = __float2bfloat16(v[2 * j]     - __bfloat162float(h0));
        __nv_bfloat16 l1 = __float2bfloat16(v[2 * j + 1] - __bfloat162float(h1));
        hw[j] = (uint32_t)*(unsigned short*)&h0 | ((uint32_t)*(unsigned short*)&h1 << 16);
        lw[j] = (uint32_t)*(unsigned short*)&l0 | ((uint32_t)*(unsigned short*)&l1 << 16);
    }
}

// ---------------- edge_index dtype detect ----------------
__global__ void detect_kernel(const int* __restrict__ p) {
    int acc = 0;
    for (int i = threadIdx.x; i < 2048; i += blockDim.x) acc |= p[2 * i + 1];
    int any = __syncthreads_or(acc);
    if (threadIdx.x == 0) g_is64 = (any == 0) ? 1 : 0;
}

__global__ void clear_cnt() {
    int i = blockIdx.x * blockDim.x + threadIdx.x;
    if (i < N_NODES) g_cnt[i] = 0;
}

__global__ void hist_kernel(const int* __restrict__ p) {
    int i = blockIdx.x * blockDim.x + threadIdx.x;
    if (i >= N_EDGES) return;
    int d = g_is64 ? p[2 * N_EDGES + 2 * i] : p[N_EDGES + i];
    atomicAdd(&g_cnt[d], 1);
}

__global__ void scanA() {
    __shared__ int sm[256];
    int i = blockIdx.x * 256 + threadIdx.x;
    sm[threadIdx.x] = (i < N_NODES) ? g_cnt[i] : 0;
    __syncthreads();
    for (int off = 128; off; off >>= 1) {
        if (threadIdx.x < off) sm[threadIdx.x] += sm[threadIdx.x + off];
        __syncthreads();
    }
    if (threadIdx.x == 0) g_bsum[blockIdx.x] = sm[0];
}

__global__ void scanB() {
    __shared__ int sm[256];
    int t = threadIdx.x;
    sm[t] = (t < NBLK) ? g_bsum[t] : 0;
    __syncthreads();
    for (int off = 1; off < 256; off <<= 1) {
        int v = (t >= off) ? sm[t - off] : 0;
        __syncthreads();
        sm[t] += v;
        __syncthreads();
    }
    if (t < NBLK) g_boff[t] = sm[t] - g_bsum[t];
}

__global__ void scanC() {
    __shared__ int sm[256];
    int t = threadIdx.x;
    int i = blockIdx.x * 256 + t;
    int c = (i < N_NODES) ? g_cnt[i] : 0;
    sm[t] = c;
    __syncthreads();
    for (int off = 1; off < 256; off <<= 1) {
        int v = (t >= off) ? sm[t - off] : 0;
        __syncthreads();
        sm[t] += v;
        __syncthreads();
    }
    if (i < N_NODES) {
        int start = g_boff[blockIdx.x] + sm[t] - c;
        g_rowoff[i] = start;
        g_cur[i] = start;
    }
    if (blockIdx.x == 0 && t == 0) g_rowoff[N_NODES] = N_EDGES;
}

__global__ void scatter_kernel(const int* __restrict__ p,
                               const float* __restrict__ eattr) {
    int i = blockIdx.x * blockDim.x + threadIdx.x;
    if (i >= N_EDGES) return;
    int s, d;
    if (g_is64) {
        s = p[2 * i];
        d = p[2 * N_EDGES + 2 * i];
    } else {
        s = p[i];
        d = p[N_EDGES + i];
    }
    int pos = atomicAdd(&g_cur[d], 1);
    g_epack[pos] = make_int2(s, __float_as_int(eattr[i]));
}

// ---------------- mma.sync GEMM: C[M,2*halfN] = A[M,K] @ [B1|B2] + bias --------
// CTA tile 128x128, K fully smem-resident as bf16 hi/lo (padded stride K+8:
// row stride mod 128B == 16 -> conflict-free ldmatrix). 8 warps, each 32x64
// via 2x8 m16n8k16 atoms; 3 accumulation passes AhBh + AhBl + AlBh.
__global__ __launch_bounds__(256) void mma_gemm(
    const float* __restrict__ A,
    const float* __restrict__ B1, const float* __restrict__ B2,
    const float* __restrict__ bias1, const float* __restrict__ bias2,
    float* __restrict__ C, int M, int K, int halfN)
{
    extern __shared__ char smem[];
    const int SK = K + 8;                           // padded stride (bf16)
    const uint32_t TILE = (uint32_t)128 * SK * 2;   // bytes per tile
    char* Ah = smem;
    char* Al = smem + TILE;
    char* Bh = smem + 2 * TILE;
    char* Bl = smem + 3 * TILE;

    int tid = threadIdx.x, wid = tid >> 5, lane = tid & 31;
    int row0 = blockIdx.y * 128, col0 = blockIdx.x * 128;
    int Ntot = 2 * halfN;
    int KC = K >> 3;

    // ---- fill A (hi/lo) ----
    for (int idx = tid; idx < 128 * KC; idx += 256) {
        int r = idx / KC, c0 = (idx - r * KC) * 8;
        float v[8];
        int gr = row0 + r;
        if (gr < M) {
            const float4* ap = (const float4*)(A + (size_t)gr * K + c0);
            float4 u0 = ap[0], u1 = ap[1];
            v[0] = u0.x; v[1] = u0.y; v[2] = u0.z; v[3] = u0.w;
            v[4] = u1.x; v[5] = u1.y; v[6] = u1.z; v[7] = u1.w;
        } else {
#pragma unroll
            for (int j = 0; j < 8; j++) v[j] = 0.f;
        }
        uint32_t hw[4], lw[4];
        bf16_split8(v, hw, lw);
        uint32_t off = (uint32_t)(r * SK + c0) * 2;
        *(uint4*)(Ah + off) = make_uint4(hw[0], hw[1], hw[2], hw[3]);
        *(uint4*)(Al + off) = make_uint4(lw[0], lw[1], lw[2], lw[3]);
    }
    // ---- fill B[n][k] = W[k][col0+n] (transposed gather), hi/lo ----
    for (int idx = tid; idx < 128 * KC; idx += 256) {
        int n = idx / KC, c0 = (idx - n * KC) * 8;
        int gn = col0 + n;
        const float* Bp = (gn < halfN) ? B1 : B2;
        int nn = (gn < halfN) ? gn : gn - halfN;
        float v[8];
#pragma unroll
        for (int j = 0; j < 8; j++) v[j] = Bp[(size_t)(c0 + j) * halfN + nn];
        uint32_t hw[4], lw[4];
        bf16_split8(v, hw, lw);
        uint32_t off = (uint32_t)(n * SK + c0) * 2;
        *(uint4*)(Bh + off) = make_uint4(hw[0], hw[1], hw[2], hw[3]);
        *(uint4*)(Bl + off) = make_uint4(lw[0], lw[1], lw[2], lw[3]);
    }
    __syncthreads();

    // ---- MMA ----
    int m_base = (wid & 3) * 32;
    int n_base = (wid >> 2) * 64;
    int aRow = lane & 15, aCol = (lane >> 4) * 8;           // A ldmatrix pattern
    int bN = (lane & 7) + ((lane >> 4) << 3);               // B ldmatrix pattern
    int bK = ((lane >> 3) & 1) * 8;

    uint32_t sb = smem_u32(smem);
    uint32_t aBase = sb + (uint32_t)((m_base + aRow) * SK + aCol) * 2;
    uint32_t bBase = sb + 2 * TILE + (uint32_t)((n_base + bN) * SK + bK) * 2;
    const uint32_t aPassOff[3] = {0, 0, TILE};      // Ah, Ah, Al
    const uint32_t bPassOff[3] = {0, TILE, 0};      // Bh, Bl, Bh

    float acc[2][8][4];
#pragma unroll
    for (int i = 0; i < 2; i++)
#pragma unroll
        for (int j = 0; j < 8; j++)
#pragma unroll
            for (int q = 0; q < 4; q++) acc[i][j][q] = 0.f;

    int nks = K >> 4;
    for (int pass = 0; pass < 3; pass++) {
        uint32_t aP = aBase + aPassOff[pass];
        uint32_t bP = bBase + bPassOff[pass];
        for (int ks = 0; ks < nks; ks++) {
            uint32_t kOff = (uint32_t)(ks * 16) * 2;
            uint32_t a[2][4];
#pragma unroll
            for (int ma = 0; ma < 2; ma++)
                LDSM_X4(a[ma], aP + kOff + (uint32_t)(ma * 16 * SK) * 2);
            uint32_t b[4][4];
#pragma unroll
            for (int nb = 0; nb < 4; nb++)
                LDSM_X4(b[nb], bP + kOff + (uint32_t)(nb * 16 * SK) * 2);
#pragma unroll
            for (int ma = 0; ma < 2; ma++)
#pragma unroll
                for (int na = 0; na < 8; na++)
                    mma_bf16(acc[ma][na], a[ma],
                             b[na >> 1][(na & 1) * 2], b[na >> 1][(na & 1) * 2 + 1]);
        }
    }

    // ---- epilogue: registers -> global, bias added ----
#pragma unroll
    for (int ma = 0; ma < 2; ma++) {
#pragma unroll
        for (int na = 0; na < 8; na++) {
            int col = col0 + n_base + na * 8 + (lane & 3) * 2;
            float b0 = (col     < halfN) ? bias1[col]     : bias2[col - halfN];
            float b1 = (col + 1 < halfN) ? bias1[col + 1] : bias2[col + 1 - halfN];
            int gr0 = row0 + m_base + ma * 16 + (lane >> 2);
            if (gr0 < M)
                *(float2*)(C + (size_t)gr0 * Ntot + col) =
                    make_float2(acc[ma][na][0] + b0, acc[ma][na][1] + b1);
            int gr1 = gr0 + 8;
            if (gr1 < M)
                *(float2*)(C + (size_t)gr1 * Ntot + col) =
                    make_float2(acc[ma][na][2] + b0, acc[ma][na][3] + b1);
        }
    }
}

// ---------------- fused GAT layer 1: warp/node, 24 lanes x 8 contiguous ch -------
__global__ __launch_bounds__(256) void gat1_kernel(
    const float* __restrict__ We, const float* __restrict__ att,
    const float* __restrict__ bias)
{
    int node = blockIdx.x * 8 + (threadIdx.x >> 5);
    int lane = threadIdx.x & 31;
    if (node >= N_NODES) return;
    int beg = g_rowoff[node], end = g_rowoff[node + 1];
    int chb = (lane < 24) ? (lane << 3) : 0;

    const float4* xrp = (const float4*)(g_xw1 + (size_t)node * 384 + 192 + chb);
    float4 xr0 = xrp[0], xr1 = xrp[1];
    float4 We0 = *(const float4*)(We + chb),  We4 = *(const float4*)(We + chb + 4);
    float4 at0 = *(const float4*)(att + chb), at4 = *(const float4*)(att + chb + 4);

    float4 acc0 = make_float4(0.f, 0.f, 0.f, 0.f);
    float4 acc1 = make_float4(0.f, 0.f, 0.f, 0.f);
    float den = 0.f;

    int e = beg;
    int2 pr = make_int2(0, 0);
    if (e < end) pr = g_epack[e];
    while (e < end) {
        int e2 = e + 1;
        int2 pr2 = make_int2(0, 0);
        if (e2 < end) pr2 = g_epack[e2];
        int s = pr.x;
        float a = __int_as_float(pr.y);

        const float4* xlp = (const float4*)(g_xw1 + (size_t)s * 384 + chb);
        float4 x0 = xlp[0], x1 = xlp[1];

        float p;
        p  = at0.x * lrelu(fmaf(a, We0.x, x0.x + xr0.x));
        p += at0.y * lrelu(fmaf(a, We0.y, x0.y + xr0.y));
        p += at0.z * lrelu(fmaf(a, We0.z, x0.z + xr0.z));
        p += at0.w * lrelu(fmaf(a, We0.w, x0.w + xr0.w));
        p += at4.x * lrelu(fmaf(a, We4.x, x1.x + xr1.x));
        p += at4.y * lrelu(fmaf(a, We4.y, x1.y + xr1.y));
        p += at4.z * lrelu(fmaf(a, We4.z, x1.z + xr1.z));
        p += at4.w * lrelu(fmaf(a, We4.w, x1.w + xr1.w));
        p += __shfl_xor_sync(0xffffffffu, p, 1);
        p += __shfl_xor_sync(0xffffffffu, p, 2);
        p += __shfl_xor_sync(0xffffffffu, p, 4);
        float w = __expf(p);
        den += w;
        acc0.x = fmaf(w, x0.x, acc0.x); acc0.y = fmaf(w, x0.y, acc0.y);
        acc0.z = fmaf(w, x0.z, acc0.z); acc0.w = fmaf(w, x0.w, acc0.w);
        acc1.x = fmaf(w, x1.x, acc1.x); acc1.y = fmaf(w, x1.y, acc1.y);
        acc1.z = fmaf(w, x1.z, acc1.z); acc1.w = fmaf(w, x1.w, acc1.w);

        pr = pr2; e = e2;
    }

    if (lane < 24) {
        float dinv = 1.f / (den + 1e-16f);
        float4 b0 = *(const float4*)(bias + chb);
        float4 b4 = *(const float4*)(bias + chb + 4);
        float4 o0, o1;
        o0.x = elu(fmaf(acc0.x, dinv, b0.x));
        o0.y = elu(fmaf(acc0.y, dinv, b0.y));
        o0.z = elu(fmaf(acc0.z, dinv, b0.z));
        o0.w = elu(fmaf(acc0.w, dinv, b0.w));
        o1.x = elu(fmaf(acc1.x, dinv, b4.x));
        o1.y = elu(fmaf(acc1.y, dinv, b4.y));
        o1.z = elu(fmaf(acc1.z, dinv, b4.z));
        o1.w = elu(fmaf(acc1.w, dinv, b4.w));
        float4* hp = (float4*)(g_h1 + (size_t)node * D1 + chb);
        hp[0] = o0; hp[1] = o1;
    }
}

// ---------------- fused GAT layer 2: warp/node, 2 edges/warp, 16 lanes x 4 ch ----
__global__ __launch_bounds__(256) void gat2_kernel(
    const float* __restrict__ We, const float* __restrict__ att,
    const float* __restrict__ bias, float* __restrict__ out)
{
    int node = blockIdx.x * 8 + (threadIdx.x >> 5);
    int lane = threadIdx.x & 31;
    if (node >= N_NODES) return;
    int beg = g_rowoff[node], end = g_rowoff[node + 1];
    int half = lane >> 4;
    int chb = (lane & 15) << 2;

    float4 xr  = *(const float4*)(g_xw2 + (size_t)node * 128 + 64 + chb);
    float4 Wev = *(const float4*)(We + chb);
    float4 atv = *(const float4*)(att + chb);

    float4 acc = make_float4(0.f, 0.f, 0.f, 0.f);
    float den = 0.f;

    int base = beg;
    int e = base + half;
    bool valid = (e < end) && (base < end);
    int2 pr = make_int2(0, 0);
    if (valid) pr = g_epack[e];
    while (base < end) {
        int base2 = base + 2;
        int e2 = base2 + half;
        bool v2 = (base2 < end) && (e2 < end);
        int2 pr2 = make_int2(0, 0);
        if (v2) pr2 = g_epack[e2];
        int s = pr.x;
        float a = __int_as_float(pr.y);

        float4 x = *(const float4*)(g_xw2 + (size_t)s * 128 + chb);
        float p;
        p  = atv.x * lrelu(fmaf(a, Wev.x, x.x + xr.x));
        p += atv.y * lrelu(fmaf(a, Wev.y, x.y + xr.y));
        p += atv.z * lrelu(fmaf(a, Wev.z, x.z + xr.z));
        p += atv.w * lrelu(fmaf(a, Wev.w, x.w + xr.w));
        p += __shfl_xor_sync(0xffffffffu, p, 1);
        p += __shfl_xor_sync(0xffffffffu, p, 2);
        p += __shfl_xor_sync(0xffffffffu, p, 4);
        p += __shfl_xor_sync(0xffffffffu, p, 8);
        float w = valid ? __expf(p) : 0.f;
        den += w;
        acc.x = fmaf(w, x.x, acc.x); acc.y = fmaf(w, x.y, acc.y);
        acc.z = fmaf(w, x.z, acc.z); acc.w = fmaf(w, x.w, acc.w);

        base = base2; pr = pr2; valid = v2;
    }

    den   += __shfl_xor_sync(0xffffffffu, den,   16);
    acc.x += __shfl_xor_sync(0xffffffffu, acc.x, 16);
    acc.y += __shfl_xor_sync(0xffffffffu, acc.y, 16);
    acc.z += __shfl_xor_sync(0xffffffffu, acc.z, 16);
    acc.w += __shfl_xor_sync(0xffffffffu, acc.w, 16);

    if (half == 0) {
        float dinv = 1.f / (den + 1e-16f);
        float4 bv = *(const float4*)(bias + chb);
        float4 o;
        o.x = elu(fmaf(acc.x, dinv, bv.x));
        o.y = elu(fmaf(acc.y, dinv, bv.y));
        o.z = elu(fmaf(acc.z, dinv, bv.z));
        o.w = elu(fmaf(acc.w, dinv, bv.w));
        *(float4*)(out + (size_t)node * OUT + chb) = o;
    }
}

// ---------------- launch ----------------
extern "C" void kernel_launch(void* const* d_in, const int* in_sizes, int n_in,
                              void* d_out, int out_size) {
    const float* x     = (const float*)d_in[0];
    const int*   eidx  = (const int*)d_in[1];
    const float* eattr = (const float*)d_in[2];
    const float* Wl1   = (const float*)d_in[3];
    const float* bl1   = (const float*)d_in[4];
    const float* Wr1   = (const float*)d_in[5];
    const float* br1   = (const float*)d_in[6];
    const float* We1   = (const float*)d_in[7];
    const float* att1  = (const float*)d_in[8];
    const float* bias1 = (const float*)d_in[9];
    const float* Wl2   = (const float*)d_in[10];
    const float* bl2   = (const float*)d_in[11];
    const float* Wr2   = (const float*)d_in[12];
    const float* br2   = (const float*)d_in[13];
    const float* We2   = (const float*)d_in[14];
    const float* att2  = (const float*)d_in[15];
    const float* bias2 = (const float*)d_in[16];
    float* out = (float*)d_out;

    static float* p_xw1 = nullptr;
    static float* p_h1  = nullptr;
    static float* p_xw2 = nullptr;
    if (!p_xw1) {
        cudaGetSymbolAddress((void**)&p_xw1, g_xw1);
        cudaGetSymbolAddress((void**)&p_h1,  g_h1);
        cudaGetSymbolAddress((void**)&p_xw2, g_xw2);
        // K=192 case: 4 tiles x 128 x 200 bf16 = 204800 bytes
        cudaFuncSetAttribute(mma_gemm,
            cudaFuncAttributeMaxDynamicSharedMemorySize, 204800);
    }

    const int ET = (N_EDGES + 255) / 256;
    const int MT = (N_NODES + 127) / 128;   // 391

    const int smem1 = 4 * 128 * (F_IN + 8) * 2;  // 139264
    const int smem2 = 4 * 128 * (D1 + 8) * 2;    // 204800

    detect_kernel<<<1, 256>>>(eidx);                 // 1
    clear_cnt<<<NBLK, 256>>>();                      // 2
    hist_kernel<<<ET, 256>>>(eidx);                  // 3
    // layer 1 GEMM 4th so ncu captures it: K=128, N=384
    mma_gemm<<<dim3(3, MT), 256, smem1>>>(
        x, Wl1, Wr1, bl1, br1, p_xw1, N_NODES, F_IN, D1);                        // 4
    scanA<<<NBLK, 256>>>();                          // 5
    scanB<<<1, 256>>>();                             // 6
    scanC<<<NBLK, 256>>>();                          // 7
    scatter_kernel<<<ET, 256>>>(eidx, eattr);        // 8
    gat1_kernel<<<(N_NODES + 7) / 8, 256>>>(We1, att1, bias1);                   // 9
    // layer 2 GEMM: K=192, N=128
    mma_gemm<<<dim3(1, MT), 256, smem2>>>(
        p_h1, Wl2, Wr2, bl2, br2, p_xw2, N_NODES, D1, OUT);                      // 10
    gat2_kernel<<<(N_NODES + 7) / 8, 256>>>(We2, att2, bias2, out);              // 11
}

// round 16
// speedup vs baseline: 1.3099x; 1.3099x over previous
#include <cuda_runtime.h>
#include <cuda_bf16.h>
#include <math.h>
#include <stdint.h>

#define N_NODES 50000
#define N_EDGES 800000
#define F_IN    128
#define HID     64
#define H1      3
#define D1      (H1*HID)        // 192
#define OUT     64
#define LRELU   0.2f
#define NBLK    ((N_NODES + 255) / 256)   // 196

// ---------------- scratch (device globals; no allocation allowed) ----------------
__device__ int   g_is64;
__device__ int   g_cnt[N_NODES];
__device__ int   g_bsum[256];
__device__ int   g_boff[256];
__device__ int   g_rowoff[N_NODES + 1];
__device__ int   g_cur[N_NODES];
__device__ int2  g_epack[N_EDGES];              // {src, float_bits(edge_attr)}
__device__ float g_xw1[(size_t)N_NODES * 384];  // [node][xl(192) | xr(192)]
__device__ float g_xw2[(size_t)N_NODES * 128];  // [node][xl(64) | xr(64)]
// bf16 hi/lo operands for tensor-core GEMMs
__device__ __nv_bfloat16 g_xh[(size_t)N_NODES * F_IN];
__device__ __nv_bfloat16 g_xl[(size_t)N_NODES * F_IN];
__device__ __nv_bfloat16 g_h1h[(size_t)N_NODES * D1];
__device__ __nv_bfloat16 g_h1l[(size_t)N_NODES * D1];
__device__ __nv_bfloat16 g_w1h[384 * F_IN];     // [n][k], n in [Wl1|Wr1]
__device__ __nv_bfloat16 g_w1l[384 * F_IN];
__device__ __nv_bfloat16 g_w2h[128 * D1];       // [n][k], n in [Wl2|Wr2]
__device__ __nv_bfloat16 g_w2l[128 * D1];

// ---------------- helpers ----------------
__device__ __forceinline__ float lrelu(float v) { return v > 0.f ? v : LRELU * v; }
__device__ __forceinline__ float elu(float v)   { return v > 0.f ? v : expm1f(v); }

__device__ __forceinline__ uint32_t smem_u32(const void* p) {
    uint32_t a;
    asm("{ .reg .u64 t; cvta.to.shared.u64 t, %1; cvt.u32.u64 %0, t; }"
        : "=r"(a) : "l"(p));
    return a;
}
#define LDSM_X4(r, addr) \
    asm volatile("ldmatrix.sync.aligned.m8n8.x4.shared.b16 {%0,%1,%2,%3}, [%4];" \
        : "=r"((r)[0]), "=r"((r)[1]), "=r"((r)[2]), "=r"((r)[3]) : "r"(addr))
#define CP_ASYNC16(dst, src, sz) \
    asm volatile("cp.async.cg.shared.global [%0], [%1], 16, %2;" \
        :: "r"(dst), "l"(src), "r"(sz) : "memory")
#define CP_COMMIT() asm volatile("cp.async.commit_group;" ::: "memory")
#define CP_WAIT0()  asm volatile("cp.async.wait_group 0;" ::: "memory")

__device__ __forceinline__ void mma_bf16(float* c, const uint32_t* a,
                                         uint32_t b0, uint32_t b1) {
    asm volatile(
        "mma.sync.aligned.m16n8k16.row.col.f32.bf16.bf16.f32 "
        "{%0,%1,%2,%3}, {%4,%5,%6,%7}, {%8,%9}, {%0,%1,%2,%3};"
        : "+f"(c[0]), "+f"(c[1]), "+f"(c[2]), "+f"(c[3])
        : "r"(a[0]), "r"(a[1]), "r"(a[2]), "r"(a[3]), "r"(b0), "r"(b1));
}

__device__ __forceinline__ void bf16_split1(float v, __nv_bfloat16& h, __nv_bfloat16& l) {
    h = __float2bfloat16(v);
    l = __float2bfloat16(v - __bfloat162float(h));
}

// ---------------- conversions ----------------
__global__ void conv_x(const float* __restrict__ x) {
    int i = blockIdx.x * blockDim.x + threadIdx.x;     // one float4 per thread
    if (i >= N_NODES * F_IN / 4) return;
    float4 v = ((const float4*)x)[i];
    __nv_bfloat16 h[4], l[4];
    bf16_split1(v.x, h[0], l[0]); bf16_split1(v.y, h[1], l[1]);
    bf16_split1(v.z, h[2], l[2]); bf16_split1(v.w, h[3], l[3]);
    ((uint2*)g_xh)[i] = *(uint2*)h;
    ((uint2*)g_xl)[i] = *(uint2*)l;
}

// weights -> transposed [n][k] hi/lo
__global__ void conv_w(const float* __restrict__ Wl1, const float* __restrict__ Wr1,
                       const float* __restrict__ Wl2, const float* __restrict__ Wr2) {
    int i = blockIdx.x * blockDim.x + threadIdx.x;
    if (i < 384 * F_IN) {
        int n = i / F_IN, k = i - n * F_IN;
        float v = (n < D1) ? Wl1[(size_t)k * D1 + n] : Wr1[(size_t)k * D1 + (n - D1)];
        __nv_bfloat16 h, l; bf16_split1(v, h, l);
        g_w1h[i] = h; g_w1l[i] = l;
    } else if (i < 384 * F_IN + 128 * D1) {
        int j = i - 384 * F_IN;
        int n = j / D1, k = j - n * D1;
        float v = (n < OUT) ? Wl2[(size_t)k * OUT + n] : Wr2[(size_t)k * OUT + (n - OUT)];
        __nv_bfloat16 h, l; bf16_split1(v, h, l);
        g_w2h[j] = h; g_w2l[j] = l;
    }
}

// ---------------- edge_index dtype detect / CSR build ----------------
__global__ void detect_kernel(const int* __restrict__ p) {
    int acc = 0;
    for (int i = threadIdx.x; i < 2048; i += blockDim.x) acc |= p[2 * i + 1];
    int any = __syncthreads_or(acc);
    if (threadIdx.x == 0) g_is64 = (any == 0) ? 1 : 0;
}

__global__ void clear_cnt() {
    int i = blockIdx.x * blockDim.x + threadIdx.x;
    if (i < N_NODES) g_cnt[i] = 0;
}

__global__ void hist_kernel(const int* __restrict__ p) {
    int i = blockIdx.x * blockDim.x + threadIdx.x;
    if (i >= N_EDGES) return;
    int d = g_is64 ? p[2 * N_EDGES + 2 * i] : p[N_EDGES + i];
    atomicAdd(&g_cnt[d], 1);
}

__global__ void scanA() {
    __shared__ int sm[256];
    int i = blockIdx.x * 256 + threadIdx.x;
    sm[threadIdx.x] = (i < N_NODES) ? g_cnt[i] : 0;
    __syncthreads();
    for (int off = 128; off; off >>= 1) {
        if (threadIdx.x < off) sm[threadIdx.x] += sm[threadIdx.x + off];
        __syncthreads();
    }
    if (threadIdx.x == 0) g_bsum[blockIdx.x] = sm[0];
}

__global__ void scanB() {
    __shared__ int sm[256];
    int t = threadIdx.x;
    sm[t] = (t < NBLK) ? g_bsum[t] : 0;
    __syncthreads();
    for (int off = 1; off < 256; off <<= 1) {
        int v = (t >= off) ? sm[t - off] : 0;
        __syncthreads();
        sm[t] += v;
        __syncthreads();
    }
    if (t < NBLK) g_boff[t] = sm[t] - g_bsum[t];
}

__global__ void scanC() {
    __shared__ int sm[256];
    int t = threadIdx.x;
    int i = blockIdx.x * 256 + t;
    int c = (i < N_NODES) ? g_cnt[i] : 0;
    sm[t] = c;
    __syncthreads();
    for (int off = 1; off < 256; off <<= 1) {
        int v = (t >= off) ? sm[t - off] : 0;
        __syncthreads();
        sm[t] += v;
        __syncthreads();
    }
    if (i < N_NODES) {
        int start = g_boff[blockIdx.x] + sm[t] - c;
        g_rowoff[i] = start;
        g_cur[i] = start;
    }
    if (blockIdx.x == 0 && t == 0) g_rowoff[N_NODES] = N_EDGES;
}

__global__ void scatter_kernel(const int* __restrict__ p,
                               const float* __restrict__ eattr) {
    int i = blockIdx.x * blockDim.x + threadIdx.x;
    if (i >= N_EDGES) return;
    int s, d;
    if (g_is64) {
        s = p[2 * i];
        d = p[2 * N_EDGES + 2 * i];
    } else {
        s = p[i];
        d = p[N_EDGES + i];
    }
    int pos = atomicAdd(&g_cur[d], 1);
    g_epack[pos] = make_int2(s, __float_as_int(eattr[i]));
}

// ---------------- mma.sync GEMM, preconverted bf16 operands, cp.async fill -----
// C[M, Ntot] = A @ B^T + bias. A: [M][K] bf16 hi/lo; B: [Ntot][K] bf16 hi/lo.
// CTA tile 128x128, 512 threads (16 warps, each 32x32), smem-resident K,
// 3 passes AhBh + AhBl + AlBh.
__global__ __launch_bounds__(512) void mma_gemm(
    const __nv_bfloat16* __restrict__ Agh, const __nv_bfloat16* __restrict__ Agl,
    const __nv_bfloat16* __restrict__ Bgh, const __nv_bfloat16* __restrict__ Bgl,
    const float* __restrict__ bias1, const float* __restrict__ bias2,
    float* __restrict__ C, int M, int K, int halfN)
{
    extern __shared__ char smem[];
    const int SK = K + 8;
    const uint32_t TILE = (uint32_t)128 * SK * 2;
    int tid = threadIdx.x, wid = tid >> 5, lane = tid & 31;
    int row0 = blockIdx.y * 128, col0 = blockIdx.x * 128;
    int Ntot = 2 * halfN;
    int CH = K >> 3;                     // 16B chunks per row
    uint32_t sb = smem_u32(smem);

    // ---- async fill: Ah, Al, Bh, Bl ----
    for (int idx = tid; idx < 128 * CH; idx += 512) {
        int r = idx / CH, c = (idx - r * CH) * 8;
        int gr = row0 + r;
        uint32_t doff = (uint32_t)(r * SK + c) * 2;
        int ok = (gr < M);
        const __nv_bfloat16* sh = Agh + (size_t)(ok ? gr : 0) * K + c;
        const __nv_bfloat16* sl = Agl + (size_t)(ok ? gr : 0) * K + c;
        int sz = ok ? 16 : 0;            // src_size 0 -> zero-fill, src unread
        CP_ASYNC16(sb + doff, sh, sz);
        CP_ASYNC16(sb + TILE + doff, sl, sz);
        int gn = col0 + r;               // B rows always valid (grid exact)
        const __nv_bfloat16* bh = Bgh + (size_t)gn * K + c;
        const __nv_bfloat16* bl = Bgl + (size_t)gn * K + c;
        CP_ASYNC16(sb + 2 * TILE + doff, bh, 16);
        CP_ASYNC16(sb + 3 * TILE + doff, bl, 16);
    }
    CP_COMMIT();
    CP_WAIT0();
    __syncthreads();

    // ---- MMA: warp (wm, wn) owns 32x32 ----
    int m_base = (wid & 3) * 32;
    int n_base = (wid >> 2) * 32;
    int aRow = lane & 15, aCol = (lane >> 4) * 8;
    int bN = (lane & 7) + ((lane >> 4) << 3);
    int bK = ((lane >> 3) & 1) * 8;

    uint32_t aBase = sb + (uint32_t)((m_base + aRow) * SK + aCol) * 2;
    uint32_t bBase = sb + 2 * TILE + (uint32_t)((n_base + bN) * SK + bK) * 2;
    const uint32_t aPassOff[3] = {0, 0, TILE};
    const uint32_t bPassOff[3] = {0, TILE, 0};

    float acc[2][4][4];
#pragma unroll
    for (int i = 0; i < 2; i++)
#pragma unroll
        for (int j = 0; j < 4; j++)
#pragma unroll
            for (int q = 0; q < 4; q++) acc[i][j][q] = 0.f;

    int nks = K >> 4;
    for (int pass = 0; pass < 3; pass++) {
        uint32_t aP = aBase + aPassOff[pass];
        uint32_t bP = bBase + bPassOff[pass];
        for (int ks = 0; ks < nks; ks++) {
            uint32_t kOff = (uint32_t)(ks * 16) * 2;
            uint32_t a[2][4];
#pragma unroll
            for (int ma = 0; ma < 2; ma++)
                LDSM_X4(a[ma], aP + kOff + (uint32_t)(ma * 16 * SK) * 2);
            uint32_t b[2][4];
#pragma unroll
            for (int nb = 0; nb < 2; nb++)
                LDSM_X4(b[nb], bP + kOff + (uint32_t)(nb * 16 * SK) * 2);
#pragma unroll
            for (int ma = 0; ma < 2; ma++)
#pragma unroll
                for (int na = 0; na < 4; na++)
                    mma_bf16(acc[ma][na], a[ma],
                             b[na >> 1][(na & 1) * 2], b[na >> 1][(na & 1) * 2 + 1]);
        }
    }

    // ---- epilogue ----
#pragma unroll
    for (int ma = 0; ma < 2; ma++) {
#pragma unroll
        for (int na = 0; na < 4; na++) {
            int col = col0 + n_base + na * 8 + (lane & 3) * 2;
            float b0 = (col     < halfN) ? bias1[col]     : bias2[col - halfN];
            float b1 = (col + 1 < halfN) ? bias1[col + 1] : bias2[col + 1 - halfN];
            int gr0 = row0 + m_base + ma * 16 + (lane >> 2);
            if (gr0 < M)
                *(float2*)(C + (size_t)gr0 * Ntot + col) =
                    make_float2(acc[ma][na][0] + b0, acc[ma][na][1] + b1);
            int gr1 = gr0 + 8;
            if (gr1 < M)
                *(float2*)(C + (size_t)gr1 * Ntot + col) =
                    make_float2(acc[ma][na][2] + b0, acc[ma][na][3] + b1);
        }
    }
}

// ---------------- fused GAT layer 1 (writes h1 as bf16 hi/lo) -------------------
__global__ __launch_bounds__(256) void gat1_kernel(
    const float* __restrict__ We, const float* __restrict__ att,
    const float* __restrict__ bias)
{
    int node = blockIdx.x * 8 + (threadIdx.x >> 5);
    int lane = threadIdx.x & 31;
    if (node >= N_NODES) return;
    int beg = g_rowoff[node], end = g_rowoff[node + 1];
    int chb = (lane < 24) ? (lane << 3) : 0;

    const float4* xrp = (const float4*)(g_xw1 + (size_t)node * 384 + 192 + chb);
    float4 xr0 = xrp[0], xr1 = xrp[1];
    float4 We0 = *(const float4*)(We + chb),  We4 = *(const float4*)(We + chb + 4);
    float4 at0 = *(const float4*)(att + chb), at4 = *(const float4*)(att + chb + 4);

    float4 acc0 = make_float4(0.f, 0.f, 0.f, 0.f);
    float4 acc1 = make_float4(0.f, 0.f, 0.f, 0.f);
    float den = 0.f;

    int e = beg;
    int2 pr = make_int2(0, 0);
    if (e < end) pr = g_epack[e];
    while (e < end) {
        int e2 = e + 1;
        int2 pr2 = make_int2(0, 0);
        if (e2 < end) pr2 = g_epack[e2];
        int s = pr.x;
        float a = __int_as_float(pr.y);

        const float4* xlp = (const float4*)(g_xw1 + (size_t)s * 384 + chb);
        float4 x0 = xlp[0], x1 = xlp[1];

        float p;
        p  = at0.x * lrelu(fmaf(a, We0.x, x0.x + xr0.x));
        p += at0.y * lrelu(fmaf(a, We0.y, x0.y + xr0.y));
        p += at0.z * lrelu(fmaf(a, We0.z, x0.z + xr0.z));
        p += at0.w * lrelu(fmaf(a, We0.w, x0.w + xr0.w));
        p += at4.x * lrelu(fmaf(a, We4.x, x1.x + xr1.x));
        p += at4.y * lrelu(fmaf(a, We4.y, x1.y + xr1.y));
        p += at4.z * lrelu(fmaf(a, We4.z, x1.z + xr1.z));
        p += at4.w * lrelu(fmaf(a, We4.w, x1.w + xr1.w));
        p += __shfl_xor_sync(0xffffffffu, p, 1);
        p += __shfl_xor_sync(0xffffffffu, p, 2);
        p += __shfl_xor_sync(0xffffffffu, p, 4);
        float w = __expf(p);
        den += w;
        acc0.x = fmaf(w, x0.x, acc0.x); acc0.y = fmaf(w, x0.y, acc0.y);
        acc0.z = fmaf(w, x0.z, acc0.z); acc0.w = fmaf(w, x0.w, acc0.w);
        acc1.x = fmaf(w, x1.x, acc1.x); acc1.y = fmaf(w, x1.y, acc1.y);
        acc1.z = fmaf(w, x1.z, acc1.z); acc1.w = fmaf(w, x1.w, acc1.w);

        pr = pr2; e = e2;
    }

    if (lane < 24) {
        float dinv = 1.f / (den + 1e-16f);
        float4 b0 = *(const float4*)(bias + chb);
        float4 b4 = *(const float4*)(bias + chb + 4);
        float o[8];
        o[0] = elu(fmaf(acc0.x, dinv, b0.x));
        o[1] = elu(fmaf(acc0.y, dinv, b0.y));
        o[2] = elu(fmaf(acc0.z, dinv, b0.z));
        o[3] = elu(fmaf(acc0.w, dinv, b0.w));
        o[4] = elu(fmaf(acc1.x, dinv, b4.x));
        o[5] = elu(fmaf(acc1.y, dinv, b4.y));
        o[6] = elu(fmaf(acc1.z, dinv, b4.z));
        o[7] = elu(fmaf(acc1.w, dinv, b4.w));
        __nv_bfloat16 hh[8], ll[8];
#pragma unroll
        for (int j = 0; j < 8; j++) bf16_split1(o[j], hh[j], ll[j]);
        size_t base = (size_t)node * D1 + chb;
        *(uint4*)(g_h1h + base) = *(uint4*)hh;
        *(uint4*)(g_h1l + base) = *(uint4*)ll;
    }
}

// ---------------- fused GAT layer 2: warp/node, 2 edges/warp, 16 lanes x 4 ch ----
__global__ __launch_bounds__(256) void gat2_kernel(
    const float* __restrict__ We, const float* __restrict__ att,
    const float* __restrict__ bias, float* __restrict__ out)
{
    int node = blockIdx.x * 8 + (threadIdx.x >> 5);
    int lane = threadIdx.x & 31;
    if (node >= N_NODES) return;
    int beg = g_rowoff[node], end = g_rowoff[node + 1];
    int half = lane >> 4;
    int chb = (lane & 15) << 2;

    float4 xr  = *(const float4*)(g_xw2 + (size_t)node * 128 + 64 + chb);
    float4 Wev = *(const float4*)(We + chb);
    float4 atv = *(const float4*)(att + chb);

    float4 acc = make_float4(0.f, 0.f, 0.f, 0.f);
    float den = 0.f;

    int base = beg;
    int e = base + half;
    bool valid = (e < end) && (base < end);
    int2 pr = make_int2(0, 0);
    if (valid) pr = g_epack[e];
    while (base < end) {
        int base2 = base + 2;
        int e2 = base2 + half;
        bool v2 = (base2 < end) && (e2 < end);
        int2 pr2 = make_int2(0, 0);
        if (v2) pr2 = g_epack[e2];
        int s = pr.x;
        float a = __int_as_float(pr.y);

        float4 x = *(const float4*)(g_xw2 + (size_t)s * 128 + chb);
        float p;
        p  = atv.x * lrelu(fmaf(a, Wev.x, x.x + xr.x));
        p += atv.y * lrelu(fmaf(a, Wev.y, x.y + xr.y));
        p += atv.z * lrelu(fmaf(a, Wev.z, x.z + xr.z));
        p += atv.w * lrelu(fmaf(a, Wev.w, x.w + xr.w));
        p += __shfl_xor_sync(0xffffffffu, p, 1);
        p += __shfl_xor_sync(0xffffffffu, p, 2);
        p += __shfl_xor_sync(0xffffffffu, p, 4);
        p += __shfl_xor_sync(0xffffffffu, p, 8);
        float w = valid ? __expf(p) : 0.f;
        den += w;
        acc.x = fmaf(w, x.x, acc.x); acc.y = fmaf(w, x.y, acc.y);
        acc.z = fmaf(w, x.z, acc.z); acc.w = fmaf(w, x.w, acc.w);

        base = base2; pr = pr2; valid = v2;
    }

    den   += __shfl_xor_sync(0xffffffffu, den,   16);
    acc.x += __shfl_xor_sync(0xffffffffu, acc.x, 16);
    acc.y += __shfl_xor_sync(0xffffffffu, acc.y, 16);
    acc.z += __shfl_xor_sync(0xffffffffu, acc.z, 16);
    acc.w += __shfl_xor_sync(0xffffffffu, acc.w, 16);

    if (half == 0) {
        float dinv = 1.f / (den + 1e-16f);
        float4 bv = *(const float4*)(bias + chb);
        float4 o;
        o.x = elu(fmaf(acc.x, dinv, bv.x));
        o.y = elu(fmaf(acc.y, dinv, bv.y));
        o.z = elu(fmaf(acc.z, dinv, bv.z));
        o.w = elu(fmaf(acc.w, dinv, bv.w));
        *(float4*)(out + (size_t)node * OUT + chb) = o;
    }
}

// ---------------- launch ----------------
extern "C" void kernel_launch(void* const* d_in, const int* in_sizes, int n_in,
                              void* d_out, int out_size) {
    const float* x     = (const float*)d_in[0];
    const int*   eidx  = (const int*)d_in[1];
    const float* eattr = (const float*)d_in[2];
    const float* Wl1   = (const float*)d_in[3];
    const float* bl1   = (const float*)d_in[4];
    const float* Wr1   = (const float*)d_in[5];
    const float* br1   = (const float*)d_in[6];
    const float* We1   = (const float*)d_in[7];
    const float* att1  = (const float*)d_in[8];
    const float* bias1 = (const float*)d_in[9];
    const float* Wl2   = (const float*)d_in[10];
    const float* bl2   = (const float*)d_in[11];
    const float* Wr2   = (const float*)d_in[12];
    const float* br2   = (const float*)d_in[13];
    const float* We2   = (const float*)d_in[14];
    const float* att2  = (const float*)d_in[15];
    const float* bias2 = (const float*)d_in[16];
    float* out = (float*)d_out;

    static float* p_xw1 = nullptr;
    static float* p_xw2 = nullptr;
    static __nv_bfloat16 *p_xh, *p_xl, *p_h1h, *p_h1l, *p_w1h, *p_w1l, *p_w2h, *p_w2l;
    if (!p_xw1) {
        cudaGetSymbolAddress((void**)&p_xw1, g_xw1);
        cudaGetSymbolAddress((void**)&p_xw2, g_xw2);
        cudaGetSymbolAddress((void**)&p_xh,  g_xh);
        cudaGetSymbolAddress((void**)&p_xl,  g_xl);
        cudaGetSymbolAddress((void**)&p_h1h, g_h1h);
        cudaGetSymbolAddress((void**)&p_h1l, g_h1l);
        cudaGetSymbolAddress((void**)&p_w1h, g_w1h);
        cudaGetSymbolAddress((void**)&p_w1l, g_w1l);
        cudaGetSymbolAddress((void**)&p_w2h, g_w2h);
        cudaGetSymbolAddress((void**)&p_w2l, g_w2l);
        // K=192: 4 tiles x 128 x 200 bf16 = 204800 bytes
        cudaFuncSetAttribute(mma_gemm,
            cudaFuncAttributeMaxDynamicSharedMemorySize, 204800);
    }

    const int ET = (N_EDGES + 255) / 256;
    const int MT = (N_NODES + 127) / 128;        // 391
    const int smem1 = 4 * 128 * (F_IN + 8) * 2;  // 139264
    const int smem2 = 4 * 128 * (D1 + 8) * 2;    // 204800

    detect_kernel<<<1, 256>>>(eidx);                                   // 1
    conv_x<<<(N_NODES * F_IN / 4 + 255) / 256, 256>>>(x);              // 2
    conv_w<<<(384 * F_IN + 128 * D1 + 255) / 256, 256>>>(Wl1, Wr1, Wl2, Wr2); // 3
    // layer 1 GEMM 4th so ncu captures it: K=128, Ntot=384
    mma_gemm<<<dim3(3, MT), 512, smem1>>>(
        p_xh, p_xl, p_w1h, p_w1l, bl1, br1, p_xw1, N_NODES, F_IN, D1); // 4
    clear_cnt<<<NBLK, 256>>>();                                        // 5
    hist_kernel<<<ET, 256>>>(eidx);                                    // 6
    scanA<<<NBLK, 256>>>();                                            // 7
    scanB<<<1, 256>>>();                                               // 8
    scanC<<<NBLK, 256>>>();                                            // 9
    scatter_kernel<<<ET, 256>>>(eidx, eattr);                          // 10
    gat1_kernel<<<(N_NODES + 7) / 8, 256>>>(We1, att1, bias1);         // 11
    // layer 2 GEMM: K=192, Ntot=128
    mma_gemm<<<dim3(1, MT), 512, smem2>>>(
        p_h1h, p_h1l, p_w2h, p_w2l, bl2, br2, p_xw2, N_NODES, D1, OUT);// 12
    gat2_kernel<<<(N_NODES + 7) / 8, 256>>>(We2, att2, bias2, out);    // 13
}